// round 9
// baseline (speedup 1.0000x reference)
#include <cuda_runtime.h>
#include <cstdint>

#define N_IMG 32
#define C_IN  128
#define H_DIM 56
#define W_DIM 56
#define P_OUT 128
#define HP (H_DIM + 2)
#define WP (W_DIM + 2)
#define BN_EPS 1e-5f
#define CSTR 132                       // class-table stride (banks spread)

// Scratch (allocation-free rule: __device__ globals)
__device__ uint4  g_apack[N_IMG * HP * WP];   // packed activations, zero border
__device__ uint4  g_wpack[P_OUT * 9];         // packed weights per tap (4 x u32)
__device__ int    g_ccls[9 * CSTR];           // per-class border corrections
__device__ float2 g_sc[P_OUT];                // (scale, offset) fused bias+BN

// full adder: sum of three bit-vectors -> sum (w1) + carry (w2). 2 LOP3s.
__device__ __forceinline__ void fa(unsigned a, unsigned b, unsigned c,
                                   unsigned &s, unsigned &cy) {
    s  = a ^ b ^ c;                       // LOP3 0x96
    cy = (a & b) | (a & c) | (b & c);     // LOP3 0xE8 (majority)
}

// 9-input CSA popcount: taps t[0..8] -> weighted popc partials (4 POPC).
__device__ __forceinline__ void popc9(const unsigned* t, int &p1, int &p2, int &p4) {
    unsigned s1a, c1a, s1b, c1b, s1c, c1c;
    fa(t[0], t[1], t[2], s1a, c1a);
    fa(t[3], t[4], t[5], s1b, c1b);
    fa(t[6], t[7], t[8], s1c, c1c);
    unsigned S1, C2a, S2, C4;
    fa(s1a, s1b, s1c, S1, C2a);     // weight 1 + weight 2
    fa(c1a, c1b, c1c, S2, C4);      // weight 2 + weight 4
    p1 += __popc(S1);
    p2 += __popc(C2a) + __popc(S2);
    p4 += __popc(C4);
}

// ---------------------------------------------------------------------------
// Pack weights (parallel): one block per output channel, ballot-based packing.
// Also emits the 9-class border-correction table and fused BN scale/offset.
// ---------------------------------------------------------------------------
__global__ void pack_w_kernel(const float* __restrict__ w,
                              const float* __restrict__ bias,
                              const float* __restrict__ gamma,
                              const float* __restrict__ beta,
                              const float* __restrict__ rmean,
                              const float* __restrict__ rvar) {
    int p = blockIdx.x;           // 0..127
    int c = threadIdx.x;          // 0..127 (input channel)
    int lane = c & 31, wd = c >> 5;

    __shared__ unsigned sw[9][4];
    __shared__ int ssum[9];

    #pragma unroll
    for (int t = 0; t < 9; t++) {
        float v = w[(size_t)(p * C_IN + c) * 9 + t];
        unsigned m = __ballot_sync(0xffffffffu, v >= 0.0f);
        if (lane == 0) sw[t][wd] = m;
    }
    __syncthreads();

    if (c < 9) {
        int t = c;
        int pc = __popc(sw[t][0]) + __popc(sw[t][1]) + __popc(sw[t][2]) + __popc(sw[t][3]);
        ssum[t] = 2 * pc - C_IN;
    }
    __syncthreads();

    if (c < 9) {
        g_wpack[p * 9 + c] = make_uint4(sw[c][0], sw[c][1], sw[c][2], sw[c][3]);
    }
    if (c == 0) {
        const int* ws = ssum;
        int top = ws[0] + ws[1] + ws[2];
        int bot = ws[6] + ws[7] + ws[8];
        int lef = ws[0] + ws[3] + ws[6];
        int rig = ws[2] + ws[5] + ws[8];
        // classes: 0=interior 1=L 2=R 3=T 4=B 5=TL 6=TR 7=BL 8=BR
        g_ccls[0 * CSTR + p] = 0;
        g_ccls[1 * CSTR + p] = lef;
        g_ccls[2 * CSTR + p] = rig;
        g_ccls[3 * CSTR + p] = top;
        g_ccls[4 * CSTR + p] = bot;
        g_ccls[5 * CSTR + p] = top + lef - ws[0];
        g_ccls[6 * CSTR + p] = top + rig - ws[2];
        g_ccls[7 * CSTR + p] = bot + lef - ws[6];
        g_ccls[8 * CSTR + p] = bot + rig - ws[8];

        float inv = gamma[p] / sqrtf(rvar[p] + BN_EPS);
        float offs = bias[p] * inv + beta[p] - rmean[p] * inv;
        g_sc[p] = make_float2(inv, offs);
    }
}

// ---------------------------------------------------------------------------
// Pack activations with 1-pixel zero border. 256 threads cover 4 padded rows.
// ---------------------------------------------------------------------------
__global__ void __launch_bounds__(256) pack_a_kernel(const float* __restrict__ x) {
    int b = blockIdx.x;                 // (n, row-quad)
    int rq = b % ((HP + 3) / 4);
    int n  = b / ((HP + 3) / 4);
    int hp = rq * 4 + (threadIdx.x >> 6);
    int wp = threadIdx.x & 63;
    if (hp >= HP || wp >= WP) return;

    uint4 out = make_uint4(0u, 0u, 0u, 0u);
    if (hp >= 1 && hp <= H_DIM && wp >= 1 && wp <= W_DIM) {
        int h = hp - 1, w = wp - 1;
        const float* base = x + (size_t)n * C_IN * H_DIM * W_DIM + h * W_DIM + w;
        unsigned int words[4] = {0u, 0u, 0u, 0u};
        #pragma unroll 8
        for (int c = 0; c < C_IN; c++) {
            float v = base[(size_t)c * H_DIM * W_DIM];
            words[c >> 5] |= (unsigned int)(v >= 0.0f) << (c & 31);
        }
        out = make_uint4(words[0], words[1], words[2], words[3]);
    }
    g_apack[(n * HP + hp) * WP + wp] = out;
}

// ---------------------------------------------------------------------------
// Fused XNOR conv + bias + BN + residual.
// CSA-compressed popcount; warp-uniform weight LDS (w = t&63, cg = t>>6);
// 2 output rows per thread; border handling via 1-LDS class table.
// ---------------------------------------------------------------------------
__global__ void __launch_bounds__(256)
conv_kernel(const float* __restrict__ x, float* __restrict__ out) {
    __shared__ uint4  s_act[4 * WP];       // 3.7 KB
    __shared__ uint4  s_w[P_OUT * 9];      // 18 KB
    __shared__ int    s_ccls[9 * CSTR];    // 4.6 KB
    __shared__ float2 s_sc[P_OUT];         // 1 KB

    int b = blockIdx.x;
    int n = b / (H_DIM / 2);
    int h0 = (b % (H_DIM / 2)) * 2;        // first of two output rows
    int t = threadIdx.x;

    for (int i = t; i < P_OUT * 9; i += 256) s_w[i] = g_wpack[i];
    for (int i = t; i < 9 * CSTR;  i += 256) s_ccls[i] = g_ccls[i];
    for (int i = t; i < P_OUT;     i += 256) s_sc[i] = g_sc[i];
    for (int i = t; i < 4 * WP;    i += 256)
        s_act[i] = g_apack[(n * HP + h0 + i / WP) * WP + (i % WP)];
    __syncthreads();

    int w = t & 63;
    int cg = t >> 6;
    if (w >= W_DIM) return;

    // 4 rows x 3 cols of packed activations in registers: xa[row][col*4+u]
    unsigned xa[4][12];
    #pragma unroll
    for (int dr = 0; dr < 4; dr++) {
        #pragma unroll
        for (int dc = 0; dc < 3; dc++) {
            uint4 v = s_act[dr * WP + w + dc];
            xa[dr][dc * 4 + 0] = v.x; xa[dr][dc * 4 + 1] = v.y;
            xa[dr][dc * 4 + 2] = v.z; xa[dr][dc * 4 + 3] = v.w;
        }
    }

    // border classes for the two rows (static per thread)
    int ft0 = (h0 == 0), fb1 = (h0 + 1 == H_DIM - 1);
    int fl = (w == 0), fr = (w == W_DIM - 1);
    int cls0 = ft0 ? (fl ? 5 : (fr ? 6 : 3)) : (fl ? 1 : (fr ? 2 : 0));
    int cls1 = fb1 ? (fl ? 7 : (fr ? 8 : 4)) : (fl ? 1 : (fr ? 2 : 0));
    const int* cc0 = &s_ccls[cls0 * CSTR];
    const int* cc1 = &s_ccls[cls1 * CSTR];

    const size_t cstride = (size_t)H_DIM * W_DIM;
    const float* xin0 = x   + ((size_t)(n * P_OUT + cg * 32) * H_DIM + h0) * W_DIM + w;
    float*       ob0  = out + ((size_t)(n * P_OUT + cg * 32) * H_DIM + h0) * W_DIM + w;

    #pragma unroll 4
    for (int i = 0; i < 32; i++) {
        int p = cg * 32 + i;

        // load 9 weight vectors (warp-uniform -> broadcast LDS.128)
        unsigned wv[9][4];
        #pragma unroll
        for (int tp = 0; tp < 9; tp++) {
            uint4 v = s_w[p * 9 + tp];
            wv[tp][0] = v.x; wv[tp][1] = v.y; wv[tp][2] = v.z; wv[tp][3] = v.w;
        }

        int p1a = 0, p2a = 0, p4a = 0;   // row h0
        int p1b = 0, p2b = 0, p4b = 0;   // row h0+1
        #pragma unroll
        for (int u = 0; u < 4; u++) {
            unsigned ta[9], tb[9];
            #pragma unroll
            for (int tp = 0; tp < 9; tp++) {
                int dr = tp / 3, dc = tp % 3;
                ta[tp] = xa[dr    ][dc * 4 + u] ^ wv[tp][u];
                tb[tp] = xa[dr + 1][dc * 4 + u] ^ wv[tp][u];
            }
            popc9(ta, p1a, p2a, p4a);
            popc9(tb, p1b, p2b, p4b);
        }
        int dot0 = 9 * C_IN + cc0[p] - 2 * (p1a + 2 * p2a + 4 * p4a);
        int dot1 = 9 * C_IN + cc1[p] - 2 * (p1b + 2 * p2b + 4 * p4b);

        float2 sc = s_sc[p];
        ob0[i * cstride]         = (float)dot0 * sc.x + sc.y + xin0[i * cstride];
        ob0[i * cstride + W_DIM] = (float)dot1 * sc.x + sc.y + xin0[i * cstride + W_DIM];
    }
}

// ---------------------------------------------------------------------------
extern "C" void kernel_launch(void* const* d_in, const int* in_sizes, int n_in,
                              void* d_out, int out_size) {
    const float* x     = (const float*)d_in[0];
    const float* w     = (const float*)d_in[1];
    const float* bias  = (const float*)d_in[2];
    const float* gamma = (const float*)d_in[3];
    const float* beta  = (const float*)d_in[4];
    const float* rmean = (const float*)d_in[5];
    const float* rvar  = (const float*)d_in[6];
    float* out = (float*)d_out;

    pack_w_kernel<<<P_OUT, 128>>>(w, bias, gamma, beta, rmean, rvar);
    pack_a_kernel<<<N_IMG * ((HP + 3) / 4), 256>>>(x);
    conv_kernel<<<N_IMG * (H_DIM / 2), 256>>>(x, out);
}

// round 10
// speedup vs baseline: 1.4946x; 1.4946x over previous
#include <cuda_runtime.h>
#include <cstdint>

#define N_IMG 32
#define C_IN  128
#define H_DIM 56
#define W_DIM 56
#define P_OUT 128
#define HP (H_DIM + 2)
#define WP (W_DIM + 2)
#define BN_EPS 1e-5f
#define CSTR 132                       // class-table stride

// Scratch (allocation-free rule: __device__ globals)
__device__ uint4  g_apack[N_IMG * HP * WP];   // packed activations, zero border
__device__ uint4  g_wpack[P_OUT * 9];         // packed weights per tap (4 x u32)
__device__ int    g_ccls[9 * CSTR];           // per-class border corrections
__device__ float2 g_sc[P_OUT];                // (scale, offset) fused bias+BN

// full adder: sum of three bit-vectors -> sum (w1) + carry (w2). 2 LOP3s.
__device__ __forceinline__ void fa(unsigned a, unsigned b, unsigned c,
                                   unsigned &s, unsigned &cy) {
    s  = a ^ b ^ c;                       // LOP3 0x96
    cy = (a & b) | (a & c) | (b & c);     // LOP3 0xE8 (majority)
}

// 9-input CSA popcount: taps t[0..8] -> weighted popc partials (4 POPC).
__device__ __forceinline__ void popc9(const unsigned* t, int &p1, int &p2, int &p4) {
    unsigned s1a, c1a, s1b, c1b, s1c, c1c;
    fa(t[0], t[1], t[2], s1a, c1a);
    fa(t[3], t[4], t[5], s1b, c1b);
    fa(t[6], t[7], t[8], s1c, c1c);
    unsigned S1, C2a, S2, C4;
    fa(s1a, s1b, s1c, S1, C2a);     // weight 1 + weight 2
    fa(c1a, c1b, c1c, S2, C4);      // weight 2 + weight 4
    p1 += __popc(S1);
    p2 += __popc(C2a) + __popc(S2);
    p4 += __popc(C4);
}

// ---------------------------------------------------------------------------
// Pack weights (parallel): one block per output channel, ballot-based packing.
// Emits the 9-class border-correction table and fused BN scale/offset.
// ---------------------------------------------------------------------------
__global__ void pack_w_kernel(const float* __restrict__ w,
                              const float* __restrict__ bias,
                              const float* __restrict__ gamma,
                              const float* __restrict__ beta,
                              const float* __restrict__ rmean,
                              const float* __restrict__ rvar) {
    int p = blockIdx.x;           // 0..127
    int c = threadIdx.x;          // 0..127 (input channel)
    int lane = c & 31, wd = c >> 5;

    __shared__ unsigned sw[9][4];
    __shared__ int ssum[9];

    #pragma unroll
    for (int t = 0; t < 9; t++) {
        float v = w[(size_t)(p * C_IN + c) * 9 + t];
        unsigned m = __ballot_sync(0xffffffffu, v >= 0.0f);
        if (lane == 0) sw[t][wd] = m;
    }
    __syncthreads();

    if (c < 9) {
        int t = c;
        int pc = __popc(sw[t][0]) + __popc(sw[t][1]) + __popc(sw[t][2]) + __popc(sw[t][3]);
        ssum[t] = 2 * pc - C_IN;
    }
    __syncthreads();

    if (c < 9) {
        g_wpack[p * 9 + c] = make_uint4(sw[c][0], sw[c][1], sw[c][2], sw[c][3]);
    }
    if (c == 0) {
        const int* ws = ssum;
        int top = ws[0] + ws[1] + ws[2];
        int bot = ws[6] + ws[7] + ws[8];
        int lef = ws[0] + ws[3] + ws[6];
        int rig = ws[2] + ws[5] + ws[8];
        // classes: 0=interior 1=L 2=R 3=T 4=B 5=TL 6=TR 7=BL 8=BR
        g_ccls[0 * CSTR + p] = 0;
        g_ccls[1 * CSTR + p] = lef;
        g_ccls[2 * CSTR + p] = rig;
        g_ccls[3 * CSTR + p] = top;
        g_ccls[4 * CSTR + p] = bot;
        g_ccls[5 * CSTR + p] = top + lef - ws[0];
        g_ccls[6 * CSTR + p] = top + rig - ws[2];
        g_ccls[7 * CSTR + p] = bot + lef - ws[6];
        g_ccls[8 * CSTR + p] = bot + rig - ws[8];

        float inv = gamma[p] / sqrtf(rvar[p] + BN_EPS);
        float offs = bias[p] * inv + beta[p] - rmean[p] * inv;
        g_sc[p] = make_float2(inv, offs);
    }
}

// ---------------------------------------------------------------------------
// Pack activations with 1-pixel zero border. 256 threads cover 4 padded rows.
// ---------------------------------------------------------------------------
__global__ void __launch_bounds__(256) pack_a_kernel(const float* __restrict__ x) {
    int b = blockIdx.x;                 // (n, row-quad)
    int rq = b % ((HP + 3) / 4);
    int n  = b / ((HP + 3) / 4);
    int hp = rq * 4 + (threadIdx.x >> 6);
    int wp = threadIdx.x & 63;
    if (hp >= HP || wp >= WP) return;

    uint4 out = make_uint4(0u, 0u, 0u, 0u);
    if (hp >= 1 && hp <= H_DIM && wp >= 1 && wp <= W_DIM) {
        int h = hp - 1, w = wp - 1;
        const float* base = x + (size_t)n * C_IN * H_DIM * W_DIM + h * W_DIM + w;
        unsigned int words[4] = {0u, 0u, 0u, 0u};
        #pragma unroll 8
        for (int c = 0; c < C_IN; c++) {
            float v = base[(size_t)c * H_DIM * W_DIM];
            words[c >> 5] |= (unsigned int)(v >= 0.0f) << (c & 31);
        }
        out = make_uint4(words[0], words[1], words[2], words[3]);
    }
    g_apack[(n * HP + hp) * WP + wp] = out;
}

// ---------------------------------------------------------------------------
// Fused XNOR conv + bias + BN + residual.
// CSA-compressed popcount; warp-uniform weight LDS (w = t&63, cg = t>>6);
// 2 output rows per thread; border handling via 1-LDS class table.
// IDENTICAL to the 131.4us round-4 kernel except the correction epilogue.
// ---------------------------------------------------------------------------
__global__ void __launch_bounds__(256)
conv_kernel(const float* __restrict__ x, float* __restrict__ out) {
    __shared__ uint4  s_act[4 * WP];       // 3.7 KB
    __shared__ uint4  s_w[P_OUT * 9];      // 18 KB
    __shared__ int    s_ccls[9 * CSTR];    // 4.6 KB
    __shared__ float2 s_sc[P_OUT];         // 1 KB

    int b = blockIdx.x;
    int n = b / (H_DIM / 2);
    int h0 = (b % (H_DIM / 2)) * 2;        // first of two output rows
    int t = threadIdx.x;

    for (int i = t; i < P_OUT * 9; i += 256) s_w[i] = g_wpack[i];
    for (int i = t; i < 9 * CSTR;  i += 256) s_ccls[i] = g_ccls[i];
    for (int i = t; i < P_OUT;     i += 256) s_sc[i] = g_sc[i];
    for (int i = t; i < 4 * WP;    i += 256)
        s_act[i] = g_apack[(n * HP + h0 + i / WP) * WP + (i % WP)];
    __syncthreads();

    int w = t & 63;
    int cg = t >> 6;
    if (w >= W_DIM) return;

    // 4 rows x 3 cols of packed activations in registers: xa[row][col*4+u]
    unsigned xa[4][12];
    #pragma unroll
    for (int dr = 0; dr < 4; dr++) {
        #pragma unroll
        for (int dc = 0; dc < 3; dc++) {
            uint4 v = s_act[dr * WP + w + dc];
            xa[dr][dc * 4 + 0] = v.x; xa[dr][dc * 4 + 1] = v.y;
            xa[dr][dc * 4 + 2] = v.z; xa[dr][dc * 4 + 3] = v.w;
        }
    }

    // border classes for the two rows (static per thread)
    int ft0 = (h0 == 0), fb1 = (h0 + 1 == H_DIM - 1);
    int fl = (w == 0), fr = (w == W_DIM - 1);
    int cls0 = ft0 ? (fl ? 5 : (fr ? 6 : 3)) : (fl ? 1 : (fr ? 2 : 0));
    int cls1 = fb1 ? (fl ? 7 : (fr ? 8 : 4)) : (fl ? 1 : (fr ? 2 : 0));
    const int* cc0 = &s_ccls[cls0 * CSTR + cg * 32];
    const int* cc1 = &s_ccls[cls1 * CSTR + cg * 32];

    const size_t cstride = (size_t)H_DIM * W_DIM;
    const float* xin0 = x   + ((size_t)(n * P_OUT + cg * 32) * H_DIM + h0) * W_DIM + w;
    float*       ob0  = out + ((size_t)(n * P_OUT + cg * 32) * H_DIM + h0) * W_DIM + w;

    #pragma unroll 2
    for (int i = 0; i < 32; i++) {
        int p = cg * 32 + i;

        // load 9 weight vectors (warp-uniform -> broadcast LDS.128)
        unsigned wv[9][4];
        #pragma unroll
        for (int tp = 0; tp < 9; tp++) {
            uint4 v = s_w[p * 9 + tp];
            wv[tp][0] = v.x; wv[tp][1] = v.y; wv[tp][2] = v.z; wv[tp][3] = v.w;
        }

        int p1a = 0, p2a = 0, p4a = 0;   // row h0
        int p1b = 0, p2b = 0, p4b = 0;   // row h0+1
        #pragma unroll
        for (int u = 0; u < 4; u++) {
            unsigned ta[9], tb[9];
            #pragma unroll
            for (int tp = 0; tp < 9; tp++) {
                int dr = tp / 3, dc = tp % 3;
                ta[tp] = xa[dr    ][dc * 4 + u] ^ wv[tp][u];
                tb[tp] = xa[dr + 1][dc * 4 + u] ^ wv[tp][u];
            }
            popc9(ta, p1a, p2a, p4a);
            popc9(tb, p1b, p2b, p4b);
        }
        int dot0 = 9 * C_IN + cc0[i] - 2 * (p1a + 2 * p2a + 4 * p4a);
        int dot1 = 9 * C_IN + cc1[i] - 2 * (p1b + 2 * p2b + 4 * p4b);

        float2 sc = s_sc[p];
        ob0[i * cstride]         = (float)dot0 * sc.x + sc.y + xin0[i * cstride];
        ob0[i * cstride + W_DIM] = (float)dot1 * sc.x + sc.y + xin0[i * cstride + W_DIM];
    }
}

// ---------------------------------------------------------------------------
extern "C" void kernel_launch(void* const* d_in, const int* in_sizes, int n_in,
                              void* d_out, int out_size) {
    const float* x     = (const float*)d_in[0];
    const float* w     = (const float*)d_in[1];
    const float* bias  = (const float*)d_in[2];
    const float* gamma = (const float*)d_in[3];
    const float* beta  = (const float*)d_in[4];
    const float* rmean = (const float*)d_in[5];
    const float* rvar  = (const float*)d_in[6];
    float* out = (float*)d_out;

    pack_w_kernel<<<P_OUT, 128>>>(w, bias, gamma, beta, rmean, rvar);
    pack_a_kernel<<<N_IMG * ((HP + 3) / 4), 256>>>(x);
    conv_kernel<<<N_IMG * (H_DIM / 2), 256>>>(x, out);
}

// round 11
// speedup vs baseline: 1.6698x; 1.1172x over previous
#include <cuda_runtime.h>
#include <cstdint>

#define N_IMG 32
#define C_IN  128
#define H_DIM 56
#define W_DIM 56
#define P_OUT 128
#define HP (H_DIM + 2)
#define WP (W_DIM + 2)
#define BN_EPS 1e-5f
#define NA_BLOCKS (N_IMG * 15)        // pack_a blocks in the fused pack kernel

// Scratch (allocation-free rule: __device__ globals)
__device__ uint4  g_apack[N_IMG * HP * WP];   // packed activations, zero border
__device__ uint4  g_wpack[P_OUT * 9];         // packed weights per tap (4 x u32)
__device__ int    g_corr[P_OUT * 8];          // border-correction values per out-channel
__device__ float2 g_sc[P_OUT];                // (scale, offset) fused bias+BN

// full adder: sum of three bit-vectors -> sum (w1) + carry (w2). 2 LOP3s.
__device__ __forceinline__ void fa(unsigned a, unsigned b, unsigned c,
                                   unsigned &s, unsigned &cy) {
    s  = a ^ b ^ c;                       // LOP3 0x96
    cy = (a & b) | (a & c) | (b & c);     // LOP3 0xE8 (majority)
}

// 9-input CSA popcount: taps t[0..8] -> weighted popc partials (4 POPC).
__device__ __forceinline__ void popc9(const unsigned* t, int &p1, int &p2, int &p4) {
    unsigned s1a, c1a, s1b, c1b, s1c, c1c;
    fa(t[0], t[1], t[2], s1a, c1a);
    fa(t[3], t[4], t[5], s1b, c1b);
    fa(t[6], t[7], t[8], s1c, c1c);
    unsigned S1, C2a, S2, C4;
    fa(s1a, s1b, s1c, S1, C2a);     // weight 1 + weight 2
    fa(c1a, c1b, c1c, S2, C4);      // weight 2 + weight 4
    p1 += __popc(S1);
    p2 += __popc(C2a) + __popc(S2);
    p4 += __popc(C4);
}

// ---------------------------------------------------------------------------
// Fused pack kernel: blocks [0, NA_BLOCKS) pack activations, blocks
// [NA_BLOCKS, NA_BLOCKS+128) pack weights + corrections + BN constants.
// ---------------------------------------------------------------------------
__global__ void __launch_bounds__(256)
pack_kernel(const float* __restrict__ x,
            const float* __restrict__ w,
            const float* __restrict__ bias,
            const float* __restrict__ gamma,
            const float* __restrict__ beta,
            const float* __restrict__ rmean,
            const float* __restrict__ rvar) {
    if (blockIdx.x < NA_BLOCKS) {
        // ---- pack activations: 1-pixel zero border, 4 padded rows per block
        int b = blockIdx.x;
        int rq = b % 15;
        int n  = b / 15;
        int hp = rq * 4 + (threadIdx.x >> 6);
        int wp = threadIdx.x & 63;
        if (hp >= HP || wp >= WP) return;

        uint4 v = make_uint4(0u, 0u, 0u, 0u);
        if (hp >= 1 && hp <= H_DIM && wp >= 1 && wp <= W_DIM) {
            int h = hp - 1, ww = wp - 1;
            const float* base = x + (size_t)n * C_IN * H_DIM * W_DIM + h * W_DIM + ww;
            unsigned int words[4] = {0u, 0u, 0u, 0u};
            #pragma unroll 8
            for (int c = 0; c < C_IN; c++) {
                float f = base[(size_t)c * H_DIM * W_DIM];
                words[c >> 5] |= (unsigned int)(f >= 0.0f) << (c & 31);
            }
            v = make_uint4(words[0], words[1], words[2], words[3]);
        }
        g_apack[(n * HP + hp) * WP + wp] = v;
    } else {
        // ---- pack weights: one block per output channel
        int p = blockIdx.x - NA_BLOCKS;   // 0..127
        int c = threadIdx.x;              // 0..255; only c<128 contribute ballots
        int lane = c & 31, wd = c >> 5;

        __shared__ unsigned sw[9][4];
        __shared__ int ssum[9];

        if (c < 128) {
            #pragma unroll
            for (int t = 0; t < 9; t++) {
                float v = w[(size_t)(p * C_IN + c) * 9 + t];
                unsigned m = __ballot_sync(0xffffffffu, v >= 0.0f);
                if (lane == 0) sw[t][wd] = m;
            }
        }
        __syncthreads();

        if (c < 9) {
            int t = c;
            int pc = __popc(sw[t][0]) + __popc(sw[t][1]) + __popc(sw[t][2]) + __popc(sw[t][3]);
            ssum[t] = 2 * pc - C_IN;
        }
        __syncthreads();

        if (c < 9) {
            g_wpack[p * 9 + c] = make_uint4(sw[c][0], sw[c][1], sw[c][2], sw[c][3]);
        }
        if (c == 0) {
            const int* ws = ssum;
            g_corr[p * 8 + 0] = ws[0] + ws[1] + ws[2];   // top row
            g_corr[p * 8 + 1] = ws[6] + ws[7] + ws[8];   // bottom row
            g_corr[p * 8 + 2] = ws[0] + ws[3] + ws[6];   // left col
            g_corr[p * 8 + 3] = ws[2] + ws[5] + ws[8];   // right col
            g_corr[p * 8 + 4] = ws[0];                   // corners
            g_corr[p * 8 + 5] = ws[2];
            g_corr[p * 8 + 6] = ws[6];
            g_corr[p * 8 + 7] = ws[8];

            float inv = gamma[p] / sqrtf(rvar[p] + BN_EPS);
            float offs = bias[p] * inv + beta[p] - rmean[p] * inv;
            g_sc[p] = make_float2(inv, offs);
        }
    }
}

// ---------------------------------------------------------------------------
// Fused XNOR conv + bias + BN + residual. Zero-idle-lane geometry:
// 224 threads = 7 full warps; thread t covers pair-column j = t of a 4-row-pair
// tile (jr = t/56 selects the row pair, w = t%56 the column). One 32-channel
// group per block (cg in blockIdx). Inner loop identical to the r4 champion:
// CSA popcount, warp-uniform weight LDS, 2 vertical pixels per thread.
// ---------------------------------------------------------------------------
__global__ void __launch_bounds__(224)
conv_kernel(const float* __restrict__ x, float* __restrict__ out) {
    __shared__ uint4  s_act[10 * WP];     // 9.3 KB (padded rows hp0..hp0+9)
    __shared__ uint4  s_w[32 * 9];        // 4.6 KB (this block's channel group)
    __shared__ int    s_corr[32 * 8];     // 1 KB
    __shared__ float2 s_sc[32];

    int b = blockIdx.x;                   // ((n*7 + rq)*4 + cg)
    int cg = b & 3;
    int rq = (b >> 2) % 7;
    int n  = b / 28;
    int cbase = cg * 32;
    int t = threadIdx.x;

    for (int i = t; i < 32 * 9; i += 224) s_w[i] = g_wpack[cbase * 9 + i];
    for (int i = t; i < 32 * 8; i += 224) s_corr[i] = g_corr[cbase * 8 + i];
    if (t < 32) s_sc[t] = g_sc[cbase + t];
    int hp0 = rq * 8;
    for (int i = t; i < 10 * WP; i += 224)
        s_act[i] = g_apack[(n * HP + hp0 + i / WP) * WP + (i % WP)];
    __syncthreads();

    int jr = t / 56;                      // row pair within tile: 0..3
    int w  = t % 56;                      // column: 0..55
    int h0 = hp0 + jr * 2;                // output row (even, 0..54)

    // 4 rows x 3 cols of packed activations in registers: xa[row][col*4+u]
    unsigned xa[4][12];
    #pragma unroll
    for (int dr = 0; dr < 4; dr++) {
        #pragma unroll
        for (int dc = 0; dc < 3; dc++) {
            uint4 v = s_act[(jr * 2 + dr) * WP + w + dc];
            xa[dr][dc * 4 + 0] = v.x; xa[dr][dc * 4 + 1] = v.y;
            xa[dr][dc * 4 + 2] = v.z; xa[dr][dc * 4 + 3] = v.w;
        }
    }

    // border flags (h0 even: never bottom; h0+1 odd >= 1: never top)
    int ft0 = (h0 == 0), fb1 = (h0 + 1 == H_DIM - 1);
    int fl = (w == 0), fr = (w == W_DIM - 1);

    const size_t cstride = (size_t)H_DIM * W_DIM;
    const float* xin0 = x   + ((size_t)(n * P_OUT + cbase) * H_DIM + h0) * W_DIM + w;
    float*       ob0  = out + ((size_t)(n * P_OUT + cbase) * H_DIM + h0) * W_DIM + w;

    #pragma unroll 2
    for (int i = 0; i < 32; i++) {
        // load 9 weight vectors (warp-uniform -> broadcast LDS.128)
        unsigned wv[9][4];
        #pragma unroll
        for (int tp = 0; tp < 9; tp++) {
            uint4 v = s_w[i * 9 + tp];
            wv[tp][0] = v.x; wv[tp][1] = v.y; wv[tp][2] = v.z; wv[tp][3] = v.w;
        }

        int p1a = 0, p2a = 0, p4a = 0;   // row h0
        int p1b = 0, p2b = 0, p4b = 0;   // row h0+1
        #pragma unroll
        for (int u = 0; u < 4; u++) {
            unsigned ta[9], tb[9];
            #pragma unroll
            for (int tp = 0; tp < 9; tp++) {
                int dr = tp / 3, dc = tp % 3;
                ta[tp] = xa[dr    ][dc * 4 + u] ^ wv[tp][u];
                tb[tp] = xa[dr + 1][dc * 4 + u] ^ wv[tp][u];
            }
            popc9(ta, p1a, p2a, p4a);
            popc9(tb, p1b, p2b, p4b);
        }
        int dot0 = 9 * C_IN - 2 * (p1a + 2 * p2a + 4 * p4a);
        int dot1 = 9 * C_IN - 2 * (p1b + 2 * p2b + 4 * p4b);

        const int* cr = &s_corr[i * 8];
        dot0 += ft0 * cr[0] + fl * cr[2] + fr * cr[3]
              - (ft0 & fl) * cr[4] - (ft0 & fr) * cr[5];
        dot1 += fb1 * cr[1] + fl * cr[2] + fr * cr[3]
              - (fb1 & fl) * cr[6] - (fb1 & fr) * cr[7];

        float2 sc = s_sc[i];
        ob0[i * cstride]         = (float)dot0 * sc.x + sc.y + xin0[i * cstride];
        ob0[i * cstride + W_DIM] = (float)dot1 * sc.x + sc.y + xin0[i * cstride + W_DIM];
    }
}

// ---------------------------------------------------------------------------
extern "C" void kernel_launch(void* const* d_in, const int* in_sizes, int n_in,
                              void* d_out, int out_size) {
    const float* x     = (const float*)d_in[0];
    const float* w     = (const float*)d_in[1];
    const float* bias  = (const float*)d_in[2];
    const float* gamma = (const float*)d_in[3];
    const float* beta  = (const float*)d_in[4];
    const float* rmean = (const float*)d_in[5];
    const float* rvar  = (const float*)d_in[6];
    float* out = (float*)d_out;

    pack_kernel<<<NA_BLOCKS + P_OUT, 256>>>(x, w, bias, gamma, beta, rmean, rvar);
    conv_kernel<<<N_IMG * 7 * 4, 224>>>(x, out);
}